// round 2
// baseline (speedup 1.0000x reference)
#include <cuda_runtime.h>
#include <math.h>

#define B_  256
#define T_  512
#define D_  512
#define H_  1024
#define BH  (B_ * H_)
#define TBH ((size_t)T_ * B_ * H_)

#define GRID 128
#define NTHR 128

// Scratch (static __device__ arrays are the sanctioned allocation-free workaround).
// g_G layout: [gate][t][b][h], gate 0=z, 1=r, 2=h_cand-input. Biases folded in.
static __device__ float g_G[3 * TBH];
static __device__ float g_h [BH];
static __device__ float g_z [BH];
static __device__ float g_rh[BH];
static __device__ unsigned g_bar;

static __device__ __forceinline__ float sigmoidf_(float x) {
    return 1.0f / (1.0f + expf(-x));
}

// Monotonic-counter grid barrier. Counter is reset to 0 by xproj_kernel (the
// preceding graph node) on every replay, so targets are deterministic.
static __device__ __forceinline__ void grid_barrier(unsigned target) {
    __syncthreads();
    if (threadIdx.x == 0) {
        __threadfence();
        atomicAdd(&g_bar, 1u);
        volatile unsigned* p = &g_bar;
        while (*p < target) { __nanosleep(32); }
    }
    __syncthreads();
}

// ---------------------------------------------------------------------------
// Phase 1: G[gate][t][b][:] = x[b][t][:] @ W_gate + bias_gate
// A = x viewed as [M=131072, K=512] (m = b*T + t), W = [512, 1024].
// BM=128, BN=128, BK=8, 256 threads, 8x8 register tile per thread.
// Also resets the grid-barrier counter for the persistent kernel.
// ---------------------------------------------------------------------------
__global__ __launch_bounds__(256) void xproj_kernel(
    const float* __restrict__ x,
    const float* __restrict__ Wz, const float* __restrict__ Wr, const float* __restrict__ Wh,
    const float* __restrict__ bz, const float* __restrict__ br, const float* __restrict__ bh)
{
    if (blockIdx.x == 0 && blockIdx.y == 0 && blockIdx.z == 0 && threadIdx.x == 0)
        g_bar = 0u;

    __shared__ float As[8][128];
    __shared__ float Bs[8][128];

    const int gate = blockIdx.z;
    const float* Wm   = (gate == 0) ? Wz : (gate == 1) ? Wr : Wh;
    const float* bias = (gate == 0) ? bz : (gate == 1) ? br : bh;

    const int m0 = blockIdx.y * 128;
    const int n0 = blockIdx.x * 128;
    const int tid = threadIdx.x;

    const int arow  = tid >> 1;          // 0..127
    const int acol  = (tid & 1) * 4;     // 0 or 4
    const int brow  = tid >> 5;          // 0..7
    const int bcol4 = (tid & 31) * 4;    // 0..124
    const int ty = tid >> 4;             // 0..15
    const int tx = tid & 15;             // 0..15

    float acc[8][8];
    #pragma unroll
    for (int i = 0; i < 8; i++)
        #pragma unroll
        for (int j = 0; j < 8; j++) acc[i][j] = 0.0f;

    for (int kk = 0; kk < D_; kk += 8) {
        float4 a4 = *(const float4*)(x + (size_t)(m0 + arow) * D_ + kk + acol);
        As[acol + 0][arow] = a4.x;
        As[acol + 1][arow] = a4.y;
        As[acol + 2][arow] = a4.z;
        As[acol + 3][arow] = a4.w;
        *(float4*)&Bs[brow][bcol4] =
            *(const float4*)(Wm + (size_t)(kk + brow) * H_ + n0 + bcol4);
        __syncthreads();

        #pragma unroll
        for (int k = 0; k < 8; k++) {
            float a[8], bb[8];
            #pragma unroll
            for (int i = 0; i < 8; i++) a[i]  = As[k][ty * 8 + i];
            #pragma unroll
            for (int j = 0; j < 8; j++) bb[j] = Bs[k][tx * 8 + j];
            #pragma unroll
            for (int i = 0; i < 8; i++)
                #pragma unroll
                for (int j = 0; j < 8; j++)
                    acc[i][j] += a[i] * bb[j];
        }
        __syncthreads();
    }

    float* Gg = g_G + (size_t)gate * TBH;
    float bb[8];
    #pragma unroll
    for (int j = 0; j < 8; j++) bb[j] = bias[n0 + tx * 8 + j];

    #pragma unroll
    for (int i = 0; i < 8; i++) {
        int m    = m0 + ty * 8 + i;
        int bidx = m >> 9;      // m / T_  (T_ = 512)
        int tidx = m & 511;     // m % T_
        float* row = Gg + ((size_t)tidx * B_ + bidx) * H_ + n0 + tx * 8;
        #pragma unroll
        for (int j = 0; j < 8; j++) row[j] = acc[i][j] + bb[j];
    }
}

// ---------------------------------------------------------------------------
// Persistent recurrence kernel: 128 co-resident CTAs, software grid barriers.
// Per step t:
//   Phase A (128 tiles 64x64 over [256, 2048]): z = sig(Gz + h@Uz),
//            rh = sig(Gr + h@Ur) * h
//   Phase B (128 tiles 32x64 over [256, 1024]): h = (1-z)h + z*tanh(Gh + rh@U)
// All mutable cross-CTA data is read via __ldcg (L2 coherence point).
// ---------------------------------------------------------------------------
__global__ __launch_bounds__(NTHR) void gru_persistent(
    const float* __restrict__ Uz, const float* __restrict__ Ur,
    const float* __restrict__ U,  float* __restrict__ out)
{
    __shared__ float As[8][64];
    __shared__ float Bs[8][64];

    const int cta = blockIdx.x;
    const int tid = threadIdx.x;
    unsigned bcount = 0;

    // ---- step 0: h = sigmoid(Gz[0]) * tanh(Gh[0])  (h0 = 0) ----
    {
        size_t base = (size_t)cta * (BH / GRID);   // 2048 per CTA
        #pragma unroll
        for (int v = 0; v < 4; v++) {
            size_t idx = base + (size_t)(v * NTHR + tid) * 4;
            float4 gz = *(const float4*)&g_G[idx];
            float4 gh = *(const float4*)&g_G[2 * TBH + idx];
            float4 h;
            h.x = sigmoidf_(gz.x) * tanhf(gh.x);
            h.y = sigmoidf_(gz.y) * tanhf(gh.y);
            h.z = sigmoidf_(gz.z) * tanhf(gh.z);
            h.w = sigmoidf_(gz.w) * tanhf(gh.w);
            *(float4*)&g_h[idx] = h;
        }
    }
    bcount++; grid_barrier(bcount * GRID);

    // Tile coordinates
    const int m0A   = (cta >> 5) * 64;        // phase A: 4 M-tiles
    const int ncolA = (cta & 31) * 64;        // 0..2047 (z | r)
    const int gateA = ncolA >> 10;            // 0 = z, 1 = r
    const int n0A   = ncolA & 1023;
    const float* Ug = gateA ? Ur : Uz;

    const int m0B = (cta >> 4) * 32;          // phase B: 8 M-tiles
    const int n0B = (cta & 15) * 64;          // 16 N-tiles

    const int arowA = tid >> 1;               // 0..63
    const int acolA = (tid & 1) * 4;
    const int brow  = tid >> 4;               // 0..7
    const int bcol4 = (tid & 15) * 4;         // 0..60
    const int ty    = tid >> 4;               // 0..7
    const int tx    = tid & 15;               // 0..15

    const int arowB = tid >> 1;               // 0..31 valid when tid < 64
    const int acolB = (tid & 1) * 4;

    for (int t = 1; t < T_; t++) {
        // ================= Phase A: acc = h @ Ug (64x64 tile, K=1024) =====
        {
            float acc[8][4];
            #pragma unroll
            for (int i = 0; i < 8; i++)
                #pragma unroll
                for (int j = 0; j < 4; j++) acc[i][j] = 0.0f;

            float4 pa = __ldcg((const float4*)(g_h + (size_t)(m0A + arowA) * H_ + acolA));
            float4 pb = *(const float4*)(Ug + (size_t)brow * H_ + n0A + bcol4);

            for (int s = 0; s < H_ / 8; s++) {
                __syncthreads();
                As[acolA + 0][arowA] = pa.x;
                As[acolA + 1][arowA] = pa.y;
                As[acolA + 2][arowA] = pa.z;
                As[acolA + 3][arowA] = pa.w;
                *(float4*)&Bs[brow][bcol4] = pb;
                __syncthreads();

                if (s < H_ / 8 - 1) {
                    int kk = (s + 1) * 8;
                    pa = __ldcg((const float4*)(g_h + (size_t)(m0A + arowA) * H_ + kk + acolA));
                    pb = *(const float4*)(Ug + (size_t)(kk + brow) * H_ + n0A + bcol4);
                }

                #pragma unroll
                for (int k = 0; k < 8; k++) {
                    float a[8], bv[4];
                    #pragma unroll
                    for (int i = 0; i < 8; i++) a[i]  = As[k][ty * 8 + i];
                    #pragma unroll
                    for (int j = 0; j < 4; j++) bv[j] = Bs[k][tx * 4 + j];
                    #pragma unroll
                    for (int i = 0; i < 8; i++)
                        #pragma unroll
                        for (int j = 0; j < 4; j++)
                            acc[i][j] += a[i] * bv[j];
                }
            }

            // Epilogue A
            const float* Gg = g_G + (size_t)gateA * TBH + (size_t)t * BH;
            #pragma unroll
            for (int i = 0; i < 8; i++) {
                int m = m0A + ty * 8 + i;
                size_t off = (size_t)m * H_ + n0A + tx * 4;
                #pragma unroll
                for (int j = 0; j < 4; j++) {
                    float s = sigmoidf_(acc[i][j] + __ldg(&Gg[off + j]));
                    if (gateA == 0) g_z[off + j]  = s;
                    else            g_rh[off + j] = s * __ldcg(&g_h[off + j]);
                }
            }
        }
        bcount++; grid_barrier(bcount * GRID);

        // ================= Phase B: acc = rh @ U (32x64 tile, K=1024) =====
        {
            float acc[4][4];
            #pragma unroll
            for (int i = 0; i < 4; i++)
                #pragma unroll
                for (int j = 0; j < 4; j++) acc[i][j] = 0.0f;

            float4 pa, pb;
            if (tid < 64)
                pa = __ldcg((const float4*)(g_rh + (size_t)(m0B + arowB) * H_ + acolB));
            pb = *(const float4*)(U + (size_t)brow * H_ + n0B + bcol4);

            for (int s = 0; s < H_ / 8; s++) {
                __syncthreads();
                if (tid < 64) {
                    As[acolB + 0][arowB] = pa.x;
                    As[acolB + 1][arowB] = pa.y;
                    As[acolB + 2][arowB] = pa.z;
                    As[acolB + 3][arowB] = pa.w;
                }
                *(float4*)&Bs[brow][bcol4] = pb;
                __syncthreads();

                if (s < H_ / 8 - 1) {
                    int kk = (s + 1) * 8;
                    if (tid < 64)
                        pa = __ldcg((const float4*)(g_rh + (size_t)(m0B + arowB) * H_ + kk + acolB));
                    pb = *(const float4*)(U + (size_t)(kk + brow) * H_ + n0B + bcol4);
                }

                #pragma unroll
                for (int k = 0; k < 8; k++) {
                    float a[4], bv[4];
                    #pragma unroll
                    for (int i = 0; i < 4; i++) a[i]  = As[k][ty * 4 + i];
                    #pragma unroll
                    for (int j = 0; j < 4; j++) bv[j] = Bs[k][tx * 4 + j];
                    #pragma unroll
                    for (int i = 0; i < 4; i++)
                        #pragma unroll
                        for (int j = 0; j < 4; j++)
                            acc[i][j] += a[i] * bv[j];
                }
            }

            // Epilogue B: h = (1-z)h + z*tanh(acc + Gh)
            const float* Gh = g_G + 2 * TBH + (size_t)t * BH;
            #pragma unroll
            for (int i = 0; i < 4; i++) {
                int m = m0B + ty * 4 + i;
                size_t off = (size_t)m * H_ + n0B + tx * 4;
                #pragma unroll
                for (int j = 0; j < 4; j++) {
                    float hc = tanhf(acc[i][j] + __ldg(&Gh[off + j]));
                    float z  = __ldcg(&g_z[off + j]);
                    float h  = __ldcg(&g_h[off + j]);
                    g_h[off + j] = (1.0f - z) * h + z * hc;
                }
            }
        }
        bcount++; grid_barrier(bcount * GRID);
    }

    // ---- copy out: d_out = g_h ----
    {
        size_t base = (size_t)cta * (BH / GRID);
        #pragma unroll
        for (int v = 0; v < 4; v++) {
            size_t idx = base + (size_t)(v * NTHR + tid) * 4;
            float4 h;
            h.x = __ldcg(&g_h[idx + 0]);
            h.y = __ldcg(&g_h[idx + 1]);
            h.z = __ldcg(&g_h[idx + 2]);
            h.w = __ldcg(&g_h[idx + 3]);
            *(float4*)&out[idx] = h;
        }
    }
}

// ---------------------------------------------------------------------------
extern "C" void kernel_launch(void* const* d_in, const int* in_sizes, int n_in,
                              void* d_out, int out_size)
{
    const float* x  = (const float*)d_in[0];  // [B,T,D]
    const float* W  = (const float*)d_in[1];  // [D,H]
    const float* U  = (const float*)d_in[2];  // [H,H]
    const float* Wz = (const float*)d_in[3];
    const float* Uz = (const float*)d_in[4];
    const float* Wr = (const float*)d_in[5];
    const float* Ur = (const float*)d_in[6];
    const float* b  = (const float*)d_in[7];
    const float* bz = (const float*)d_in[8];
    const float* br = (const float*)d_in[9];

    (void)in_sizes; (void)n_in; (void)out_size;

    // Node 1: all input projections (biases folded), + barrier-counter reset.
    dim3 g1(H_ / 128, (B_ * T_) / 128, 3);
    xproj_kernel<<<g1, 256>>>(x, Wz, Wr, W, bz, br, b);

    // Node 2: entire recurrence in one persistent kernel.
    gru_persistent<<<GRID, NTHR>>>(Uz, Ur, U, (float*)d_out);
}

// round 5
// speedup vs baseline: 1.2419x; 1.2419x over previous
#include <cuda_runtime.h>
#include <math.h>

#define B_  256
#define T_  512
#define D_  512
#define H_  1024
#define BH  (B_ * H_)
#define TBH ((size_t)T_ * B_ * H_)

#define GRID 128
#define NTHR 256

typedef unsigned long long ull;

// Scratch. g_G layout: [gate][t][b][h], gate 0=z, 1=r, 2=h_cand. Biases folded.
static __device__ float g_G[3 * TBH];
static __device__ float g_h [BH];
static __device__ float g_z [BH];
static __device__ float g_rh[BH];
static __device__ unsigned g_bar;

static __device__ __forceinline__ float sigmoidf_(float x) {
    return 1.0f / (1.0f + expf(-x));
}

// Packed fp32x2 FMA (Blackwell; PTX-only — ptxas never auto-fuses).
static __device__ __forceinline__ ull fma2_(ull a, ull b, ull c) {
    ull d;
    asm("fma.rn.f32x2 %0, %1, %2, %3;" : "=l"(d) : "l"(a), "l"(b), "l"(c));
    return d;
}
static __device__ __forceinline__ ull dup2_(float x) {
    ull d;
    asm("mov.b64 %0, {%1, %2};" : "=l"(d) : "f"(x), "f"(x));
    return d;
}
static __device__ __forceinline__ float2 unpack2_(ull v) {
    float2 r;
    asm("mov.b64 {%0, %1}, %2;" : "=f"(r.x), "=f"(r.y) : "l"(v));
    return r;
}

// Monotonic-counter grid barrier (counter reset by xproj_kernel each replay).
static __device__ __forceinline__ void grid_barrier(unsigned target) {
    __syncthreads();
    if (threadIdx.x == 0) {
        __threadfence();
        atomicAdd(&g_bar, 1u);
        volatile unsigned* p = &g_bar;
        while (*p < target) { __nanosleep(32); }
    }
    __syncthreads();
}

// ---------------------------------------------------------------------------
// Phase 1: G[gate][t][b][:] = x[b][t][:] @ W_gate + bias_gate
// M=131072 (m=b*T+t), K=512, N=1024. BM=128,BN=128,BK=8, 256 thr, 8x8/thread.
// FFMA2 math, double-buffered smem, single sync per K-block.
// ---------------------------------------------------------------------------
__global__ __launch_bounds__(256) void xproj_kernel(
    const float* __restrict__ x,
    const float* __restrict__ Wz, const float* __restrict__ Wr, const float* __restrict__ Wh,
    const float* __restrict__ bz, const float* __restrict__ br, const float* __restrict__ bh)
{
    if (blockIdx.x == 0 && blockIdx.y == 0 && blockIdx.z == 0 && threadIdx.x == 0)
        g_bar = 0u;

    __shared__ float As[2][8][132];   // padded: transpose stores conflict-free
    __shared__ float Bs[2][8][128];

    const int gate = blockIdx.z;
    const float* Wm   = (gate == 0) ? Wz : (gate == 1) ? Wr : Wh;
    const float* bias = (gate == 0) ? bz : (gate == 1) ? br : bh;

    const int m0 = blockIdx.y * 128;
    const int n0 = blockIdx.x * 128;
    const int tid = threadIdx.x;

    const int arow  = tid >> 1;          // 0..127
    const int acol  = (tid & 1) * 4;     // 0 or 4
    const int brow  = tid >> 5;          // 0..7
    const int bcol4 = (tid & 31) * 4;    // 0..124
    const int ty = tid >> 4;             // 0..15
    const int tx = tid & 15;             // 0..15

    ull acc2[4][8];                      // row-pairs x 8 cols
    #pragma unroll
    for (int i = 0; i < 4; i++)
        #pragma unroll
        for (int j = 0; j < 8; j++) acc2[i][j] = 0ull;

    float4 pa = *(const float4*)(x + (size_t)(m0 + arow) * D_ + acol);
    float4 pb = *(const float4*)(Wm + (size_t)brow * H_ + n0 + bcol4);

    for (int s = 0; s < D_ / 8; s++) {
        const int buf = s & 1;
        As[buf][acol + 0][arow] = pa.x;
        As[buf][acol + 1][arow] = pa.y;
        As[buf][acol + 2][arow] = pa.z;
        As[buf][acol + 3][arow] = pa.w;
        *(float4*)&Bs[buf][brow][bcol4] = pb;
        __syncthreads();

        if (s < D_ / 8 - 1) {
            int kk = (s + 1) * 8;
            pa = *(const float4*)(x + (size_t)(m0 + arow) * D_ + kk + acol);
            pb = *(const float4*)(Wm + (size_t)(kk + brow) * H_ + n0 + bcol4);
        }

        #pragma unroll
        for (int k = 0; k < 8; k++) {
            ulonglong2 ap0 = *(const ulonglong2*)&As[buf][k][ty * 8];
            ulonglong2 ap1 = *(const ulonglong2*)&As[buf][k][ty * 8 + 4];
            float4 bv0 = *(const float4*)&Bs[buf][k][tx * 8];
            float4 bv1 = *(const float4*)&Bs[buf][k][tx * 8 + 4];
            ull bd[8];
            bd[0] = dup2_(bv0.x); bd[1] = dup2_(bv0.y);
            bd[2] = dup2_(bv0.z); bd[3] = dup2_(bv0.w);
            bd[4] = dup2_(bv1.x); bd[5] = dup2_(bv1.y);
            bd[6] = dup2_(bv1.z); bd[7] = dup2_(bv1.w);
            #pragma unroll
            for (int j = 0; j < 8; j++) {
                acc2[0][j] = fma2_(ap0.x, bd[j], acc2[0][j]);
                acc2[1][j] = fma2_(ap0.y, bd[j], acc2[1][j]);
                acc2[2][j] = fma2_(ap1.x, bd[j], acc2[2][j]);
                acc2[3][j] = fma2_(ap1.y, bd[j], acc2[3][j]);
            }
        }
    }

    float accf[8][8];
    #pragma unroll
    for (int mp = 0; mp < 4; mp++)
        #pragma unroll
        for (int j = 0; j < 8; j++) {
            float2 v = unpack2_(acc2[mp][j]);
            accf[2 * mp + 0][j] = v.x;
            accf[2 * mp + 1][j] = v.y;
        }

    float* Gg = g_G + (size_t)gate * TBH;
    float bb[8];
    #pragma unroll
    for (int j = 0; j < 8; j++) bb[j] = bias[n0 + tx * 8 + j];

    #pragma unroll
    for (int i = 0; i < 8; i++) {
        int m    = m0 + ty * 8 + i;
        int bidx = m >> 9;      // m / 512
        int tidx = m & 511;     // m % 512
        float* row = Gg + ((size_t)tidx * B_ + bidx) * H_ + n0 + tx * 8;
        #pragma unroll
        for (int j = 0; j < 8; j++) row[j] = accf[i][j] + bb[j];
    }
}

// ---------------------------------------------------------------------------
// Persistent recurrence: 128 CTAs x 256 threads, software grid barriers.
// Phase A (128 tiles 64x64 over [256,2048]): z / rh.  BK=16, FFMA2, dbl-buf.
// Phase B (128 tiles 32x64 over [256,1024]): h update.
// Cross-CTA mutable data read via __ldcg (L2 = coherence point).
// ---------------------------------------------------------------------------
__global__ __launch_bounds__(NTHR) void gru_persistent(
    const float* __restrict__ Uz, const float* __restrict__ Ur,
    const float* __restrict__ U,  float* __restrict__ out)
{
    __shared__ float As[2][16][68];   // padded
    __shared__ float Bs[2][16][64];

    const int cta = blockIdx.x;
    const int tid = threadIdx.x;
    unsigned bcount = 0;

    // ---- step 0: h = sigmoid(Gz[0]) * tanh(Gh[0])  (h0 = 0) ----
    {
        size_t base = (size_t)cta * (BH / GRID);   // 2048 per CTA
        #pragma unroll
        for (int v = 0; v < 2; v++) {
            size_t idx = base + (size_t)(v * NTHR + tid) * 4;
            float4 gz = *(const float4*)&g_G[idx];
            float4 gh = *(const float4*)&g_G[2 * TBH + idx];
            float4 h;
            h.x = sigmoidf_(gz.x) * tanhf(gh.x);
            h.y = sigmoidf_(gz.y) * tanhf(gh.y);
            h.z = sigmoidf_(gz.z) * tanhf(gh.z);
            h.w = sigmoidf_(gz.w) * tanhf(gh.w);
            *(float4*)&g_h[idx] = h;
        }
    }
    bcount++; grid_barrier(bcount * GRID);

    // Tile coordinates
    const int m0A   = (cta >> 5) * 64;        // 4 M-tiles
    const int ncolA = (cta & 31) * 64;        // 0..2047 (z | r)
    const int gateA = ncolA >> 10;            // 0 = z, 1 = r
    const int n0A   = ncolA & 1023;
    const float* Ug = gateA ? Ur : Uz;

    const int m0B = (cta >> 4) * 32;          // 8 M-tiles
    const int n0B = (cta & 15) * 64;          // 16 N-tiles

    // Loader indices (phase A): A tile 64x16, B tile 16x64
    const int arowA = tid >> 2;               // 0..63
    const int acolA = (tid & 3) * 4;          // 0,4,8,12
    const int browA = tid >> 4;               // 0..15
    const int bcolA = (tid & 15) * 4;         // 0..60
    // Compute indices
    const int ty = tid >> 4;                  // 0..15
    const int tx = tid & 15;                  // 0..15
    // Loader indices (phase B): A tile 32x16 (first 128 threads)
    const int arowB = tid >> 2;               // 0..31 (tid<128)
    const int acolB = (tid & 3) * 4;

    for (int t = 1; t < T_; t++) {
        // ===== Phase A: acc = h @ Ug, 64x64 tile, K=1024, BK=16 ==========
        {
            ull acc2[2][4];
            #pragma unroll
            for (int i = 0; i < 2; i++)
                #pragma unroll
                for (int j = 0; j < 4; j++) acc2[i][j] = 0ull;

            float4 pa = __ldcg((const float4*)(g_h + (size_t)(m0A + arowA) * H_ + acolA));
            float4 pb = *(const float4*)(Ug + (size_t)browA * H_ + n0A + bcolA);

            for (int s = 0; s < H_ / 16; s++) {
                const int buf = s & 1;
                As[buf][acolA + 0][arowA] = pa.x;
                As[buf][acolA + 1][arowA] = pa.y;
                As[buf][acolA + 2][arowA] = pa.z;
                As[buf][acolA + 3][arowA] = pa.w;
                *(float4*)&Bs[buf][browA][bcolA] = pb;
                __syncthreads();

                if (s < H_ / 16 - 1) {
                    int kk = (s + 1) * 16;
                    pa = __ldcg((const float4*)(g_h + (size_t)(m0A + arowA) * H_ + kk + acolA));
                    pb = *(const float4*)(Ug + (size_t)(kk + browA) * H_ + n0A + bcolA);
                }

                #pragma unroll
                for (int k = 0; k < 16; k++) {
                    ulonglong2 ap = *(const ulonglong2*)&As[buf][k][ty * 4];
                    float4 bv = *(const float4*)&Bs[buf][k][tx * 4];
                    ull b0 = dup2_(bv.x), b1 = dup2_(bv.y);
                    ull b2 = dup2_(bv.z), b3 = dup2_(bv.w);
                    acc2[0][0] = fma2_(ap.x, b0, acc2[0][0]);
                    acc2[0][1] = fma2_(ap.x, b1, acc2[0][1]);
                    acc2[0][2] = fma2_(ap.x, b2, acc2[0][2]);
                    acc2[0][3] = fma2_(ap.x, b3, acc2[0][3]);
                    acc2[1][0] = fma2_(ap.y, b0, acc2[1][0]);
                    acc2[1][1] = fma2_(ap.y, b1, acc2[1][1]);
                    acc2[1][2] = fma2_(ap.y, b2, acc2[1][2]);
                    acc2[1][3] = fma2_(ap.y, b3, acc2[1][3]);
                }
            }

            // Epilogue A: rows ty*4 + {0..3}, cols tx*4 + {0..3}
            float accf[4][4];
            #pragma unroll
            for (int mp = 0; mp < 2; mp++)
                #pragma unroll
                for (int j = 0; j < 4; j++) {
                    float2 v = unpack2_(acc2[mp][j]);
                    accf[2 * mp + 0][j] = v.x;
                    accf[2 * mp + 1][j] = v.y;
                }

            const float* Gg = g_G + (size_t)gateA * TBH + (size_t)t * BH;
            #pragma unroll
            for (int i = 0; i < 4; i++) {
                int m = m0A + ty * 4 + i;
                size_t off = (size_t)m * H_ + n0A + tx * 4;
                #pragma unroll
                for (int j = 0; j < 4; j++) {
                    float sg = sigmoidf_(accf[i][j] + __ldg(&Gg[off + j]));
                    if (gateA == 0) g_z[off + j]  = sg;
                    else            g_rh[off + j] = sg * __ldcg(&g_h[off + j]);
                }
            }
        }
        bcount++; grid_barrier(bcount * GRID);

        // ===== Phase B: acc = rh @ U, 32x64 tile, K=1024, BK=16 ==========
        {
            ull acc2[4];
            #pragma unroll
            for (int j = 0; j < 4; j++) acc2[j] = 0ull;

            float4 pa, pb;
            if (tid < 128)
                pa = __ldcg((const float4*)(g_rh + (size_t)(m0B + arowB) * H_ + acolB));
            pb = *(const float4*)(U + (size_t)browA * H_ + n0B + bcolA);

            for (int s = 0; s < H_ / 16; s++) {
                const int buf = s & 1;
                if (tid < 128) {
                    As[buf][acolB + 0][arowB] = pa.x;
                    As[buf][acolB + 1][arowB] = pa.y;
                    As[buf][acolB + 2][arowB] = pa.z;
                    As[buf][acolB + 3][arowB] = pa.w;
                }
                *(float4*)&Bs[buf][browA][bcolA] = pb;
                __syncthreads();

                if (s < H_ / 16 - 1) {
                    int kk = (s + 1) * 16;
                    if (tid < 128)
                        pa = __ldcg((const float4*)(g_rh + (size_t)(m0B + arowB) * H_ + kk + acolB));
                    pb = *(const float4*)(U + (size_t)(kk + browA) * H_ + n0B + bcolA);
                }

                #pragma unroll
                for (int k = 0; k < 16; k++) {
                    ull ap = *(const ull*)&As[buf][k][ty * 2];
                    float4 bv = *(const float4*)&Bs[buf][k][tx * 4];
                    acc2[0] = fma2_(ap, dup2_(bv.x), acc2[0]);
                    acc2[1] = fma2_(ap, dup2_(bv.y), acc2[1]);
                    acc2[2] = fma2_(ap, dup2_(bv.z), acc2[2]);
                    acc2[3] = fma2_(ap, dup2_(bv.w), acc2[3]);
                }
            }

            // Epilogue B: rows ty*2 + {0,1}, cols tx*4 + {0..3}
            float accf[2][4];
            #pragma unroll
            for (int j = 0; j < 4; j++) {
                float2 v = unpack2_(acc2[j]);
                accf[0][j] = v.x;
                accf[1][j] = v.y;
            }

            const float* Gh = g_G + 2 * TBH + (size_t)t * BH;
            #pragma unroll
            for (int i = 0; i < 2; i++) {
                int m = m0B + ty * 2 + i;
                size_t off = (size_t)m * H_ + n0B + tx * 4;
                #pragma unroll
                for (int j = 0; j < 4; j++) {
                    float hc = tanhf(accf[i][j] + __ldg(&Gh[off + j]));
                    float z  = __ldcg(&g_z[off + j]);
                    float h  = __ldcg(&g_h[off + j]);
                    g_h[off + j] = (1.0f - z) * h + z * hc;
                }
            }
        }
        bcount++; grid_barrier(bcount * GRID);
    }

    // ---- copy out ----
    {
        size_t base = (size_t)cta * (BH / GRID);
        #pragma unroll
        for (int v = 0; v < 2; v++) {
            size_t idx = base + (size_t)(v * NTHR + tid) * 4;
            float4 h;
            h.x = __ldcg(&g_h[idx + 0]);
            h.y = __ldcg(&g_h[idx + 1]);
            h.z = __ldcg(&g_h[idx + 2]);
            h.w = __ldcg(&g_h[idx + 3]);
            *(float4*)&out[idx] = h;
        }
    }
}

// ---------------------------------------------------------------------------
extern "C" void kernel_launch(void* const* d_in, const int* in_sizes, int n_in,
                              void* d_out, int out_size)
{
    const float* x  = (const float*)d_in[0];  // [B,T,D]
    const float* W  = (const float*)d_in[1];  // [D,H]
    const float* U  = (const float*)d_in[2];  // [H,H]
    const float* Wz = (const float*)d_in[3];
    const float* Uz = (const float*)d_in[4];
    const float* Wr = (const float*)d_in[5];
    const float* Ur = (const float*)d_in[6];
    const float* b  = (const float*)d_in[7];
    const float* bz = (const float*)d_in[8];
    const float* br = (const float*)d_in[9];

    (void)in_sizes; (void)n_in; (void)out_size;

    // Node 1: input projections (biases folded) + barrier-counter reset.
    dim3 g1(H_ / 128, (B_ * T_) / 128, 3);
    xproj_kernel<<<g1, 256>>>(x, Wz, Wr, W, bz, br, b);

    // Node 2: entire recurrence, one persistent kernel.
    gru_persistent<<<GRID, NTHR>>>(Uz, Ur, U, (float*)d_out);
}

// round 10
// speedup vs baseline: 1.8039x; 1.4525x over previous
#include <cuda_runtime.h>
#include <math.h>

#define B_  256
#define T_  512
#define D_  512
#define H_  1024
#define BH  (B_ * H_)
#define TBH ((size_t)T_ * B_ * H_)

#define GRID 128
#define NTHR 256

typedef unsigned long long ull;

// Scratch. g_G layout: [gate][t][b][h], gate 0=z, 1=r, 2=h_cand. Biases folded.
static __device__ float g_G[3 * TBH];
static __device__ float g_h [BH];
static __device__ float g_z [BH];
static __device__ float g_rh[BH];
static __device__ float g_PA[4u * 256 * 2048];   // phase-A split-K partials (8MB)
static __device__ float g_PB[8u * 256 * 1024];   // phase-B split-K partials (8MB)
static __device__ unsigned g_bar;

static __device__ __forceinline__ float sigmoidf_(float x) {
    return 1.0f / (1.0f + expf(-x));
}

// Packed fp32x2 FMA (Blackwell; PTX-only — ptxas never auto-fuses).
static __device__ __forceinline__ ull fma2_(ull a, ull b, ull c) {
    ull d;
    asm("fma.rn.f32x2 %0, %1, %2, %3;" : "=l"(d) : "l"(a), "l"(b), "l"(c));
    return d;
}
static __device__ __forceinline__ ull dup2_(float x) {
    ull d;
    asm("mov.b64 %0, {%1, %2};" : "=l"(d) : "f"(x), "f"(x));
    return d;
}
static __device__ __forceinline__ float2 unpack2_(ull v) {
    float2 r;
    asm("mov.b64 {%0, %1}, %2;" : "=f"(r.x), "=f"(r.y) : "l"(v));
    return r;
}

// Monotonic-counter grid barrier (counter reset by xproj_kernel each replay).
static __device__ __forceinline__ void grid_barrier(unsigned target) {
    __syncthreads();
    if (threadIdx.x == 0) {
        __threadfence();
        atomicAdd(&g_bar, 1u);
        volatile unsigned* p = &g_bar;
        while (*p < target) { __nanosleep(32); }
    }
    __syncthreads();
}

// ---------------------------------------------------------------------------
// Phase 1: G[gate][t][b][:] = x[b][t][:] @ W_gate + bias_gate  (unchanged)
// ---------------------------------------------------------------------------
__global__ __launch_bounds__(256) void xproj_kernel(
    const float* __restrict__ x,
    const float* __restrict__ Wz, const float* __restrict__ Wr, const float* __restrict__ Wh,
    const float* __restrict__ bz, const float* __restrict__ br, const float* __restrict__ bh)
{
    if (blockIdx.x == 0 && blockIdx.y == 0 && blockIdx.z == 0 && threadIdx.x == 0)
        g_bar = 0u;

    __shared__ float As[2][8][132];
    __shared__ float Bs[2][8][128];

    const int gate = blockIdx.z;
    const float* Wm   = (gate == 0) ? Wz : (gate == 1) ? Wr : Wh;
    const float* bias = (gate == 0) ? bz : (gate == 1) ? br : bh;

    const int m0 = blockIdx.y * 128;
    const int n0 = blockIdx.x * 128;
    const int tid = threadIdx.x;

    const int arow  = tid >> 1;
    const int acol  = (tid & 1) * 4;
    const int brow  = tid >> 5;
    const int bcol4 = (tid & 31) * 4;
    const int ty = tid >> 4;
    const int tx = tid & 15;

    ull acc2[4][8];
    #pragma unroll
    for (int i = 0; i < 4; i++)
        #pragma unroll
        for (int j = 0; j < 8; j++) acc2[i][j] = 0ull;

    float4 pa = *(const float4*)(x + (size_t)(m0 + arow) * D_ + acol);
    float4 pb = *(const float4*)(Wm + (size_t)brow * H_ + n0 + bcol4);

    for (int s = 0; s < D_ / 8; s++) {
        const int buf = s & 1;
        As[buf][acol + 0][arow] = pa.x;
        As[buf][acol + 1][arow] = pa.y;
        As[buf][acol + 2][arow] = pa.z;
        As[buf][acol + 3][arow] = pa.w;
        *(float4*)&Bs[buf][brow][bcol4] = pb;
        __syncthreads();

        if (s < D_ / 8 - 1) {
            int kk = (s + 1) * 8;
            pa = *(const float4*)(x + (size_t)(m0 + arow) * D_ + kk + acol);
            pb = *(const float4*)(Wm + (size_t)(kk + brow) * H_ + n0 + bcol4);
        }

        #pragma unroll
        for (int k = 0; k < 8; k++) {
            ulonglong2 ap0 = *(const ulonglong2*)&As[buf][k][ty * 8];
            ulonglong2 ap1 = *(const ulonglong2*)&As[buf][k][ty * 8 + 4];
            float4 bv0 = *(const float4*)&Bs[buf][k][tx * 8];
            float4 bv1 = *(const float4*)&Bs[buf][k][tx * 8 + 4];
            ull bd[8];
            bd[0] = dup2_(bv0.x); bd[1] = dup2_(bv0.y);
            bd[2] = dup2_(bv0.z); bd[3] = dup2_(bv0.w);
            bd[4] = dup2_(bv1.x); bd[5] = dup2_(bv1.y);
            bd[6] = dup2_(bv1.z); bd[7] = dup2_(bv1.w);
            #pragma unroll
            for (int j = 0; j < 8; j++) {
                acc2[0][j] = fma2_(ap0.x, bd[j], acc2[0][j]);
                acc2[1][j] = fma2_(ap0.y, bd[j], acc2[1][j]);
                acc2[2][j] = fma2_(ap1.x, bd[j], acc2[2][j]);
                acc2[3][j] = fma2_(ap1.y, bd[j], acc2[3][j]);
            }
        }
    }

    float accf[8][8];
    #pragma unroll
    for (int mp = 0; mp < 4; mp++)
        #pragma unroll
        for (int j = 0; j < 8; j++) {
            float2 v = unpack2_(acc2[mp][j]);
            accf[2 * mp + 0][j] = v.x;
            accf[2 * mp + 1][j] = v.y;
        }

    float* Gg = g_G + (size_t)gate * TBH;
    float bb[8];
    #pragma unroll
    for (int j = 0; j < 8; j++) bb[j] = bias[n0 + tx * 8 + j];

    #pragma unroll
    for (int i = 0; i < 8; i++) {
        int m    = m0 + ty * 8 + i;
        int bidx = m >> 9;
        int tidx = m & 511;
        float* row = Gg + ((size_t)tidx * B_ + bidx) * H_ + n0 + tx * 8;
        #pragma unroll
        for (int j = 0; j < 8; j++) row[j] = accf[i][j] + bb[j];
    }
}

// ---------------------------------------------------------------------------
// 128x128 partial-GEMM tile, K-chunk = kblocks*16, FFMA2 8x8/thread.
// A (mutable, __ldcg): rows stride H_.  B (weights, __ldg): rows stride H_.
// ---------------------------------------------------------------------------
static __device__ __forceinline__ void gemm128_tile(
    const float* __restrict__ A, const float* __restrict__ B,
    float* __restrict__ outp, int outStride, int kblocks,
    float (*As)[16][136], float (*Bs)[16][128], int tid)
{
    const int arow = tid >> 1;          // 0..127
    const int ac8  = (tid & 1) * 8;     // 0 or 8
    const int brow = tid >> 4;          // 0..15
    const int bc8  = (tid & 15) * 8;    // 0..120
    const int ty   = tid >> 4;          // 0..15
    const int tx   = tid & 15;          // 0..15

    ull acc2[4][8];
    #pragma unroll
    for (int i = 0; i < 4; i++)
        #pragma unroll
        for (int j = 0; j < 8; j++) acc2[i][j] = 0ull;

    float4 pa0 = __ldcg((const float4*)(A + (size_t)arow * H_ + ac8));
    float4 pa1 = __ldcg((const float4*)(A + (size_t)arow * H_ + ac8 + 4));
    float4 pb0 = __ldg ((const float4*)(B + (size_t)brow * H_ + bc8));
    float4 pb1 = __ldg ((const float4*)(B + (size_t)brow * H_ + bc8 + 4));

    for (int s = 0; s < kblocks; s++) {
        const int buf = s & 1;
        As[buf][ac8 + 0][arow] = pa0.x;
        As[buf][ac8 + 1][arow] = pa0.y;
        As[buf][ac8 + 2][arow] = pa0.z;
        As[buf][ac8 + 3][arow] = pa0.w;
        As[buf][ac8 + 4][arow] = pa1.x;
        As[buf][ac8 + 5][arow] = pa1.y;
        As[buf][ac8 + 6][arow] = pa1.z;
        As[buf][ac8 + 7][arow] = pa1.w;
        *(float4*)&Bs[buf][brow][bc8]     = pb0;
        *(float4*)&Bs[buf][brow][bc8 + 4] = pb1;
        __syncthreads();

        if (s + 1 < kblocks) {
            int kk = (s + 1) * 16;
            pa0 = __ldcg((const float4*)(A + (size_t)arow * H_ + kk + ac8));
            pa1 = __ldcg((const float4*)(A + (size_t)arow * H_ + kk + ac8 + 4));
            pb0 = __ldg ((const float4*)(B + (size_t)(kk + brow) * H_ + bc8));
            pb1 = __ldg ((const float4*)(B + (size_t)(kk + brow) * H_ + bc8 + 4));
        }

        #pragma unroll
        for (int k = 0; k < 16; k++) {
            ulonglong2 a01 = *(const ulonglong2*)&As[buf][k][ty * 8];
            ulonglong2 a23 = *(const ulonglong2*)&As[buf][k][ty * 8 + 4];
            float4 b0 = *(const float4*)&Bs[buf][k][tx * 8];
            float4 b1 = *(const float4*)&Bs[buf][k][tx * 8 + 4];
            ull bd[8];
            bd[0] = dup2_(b0.x); bd[1] = dup2_(b0.y);
            bd[2] = dup2_(b0.z); bd[3] = dup2_(b0.w);
            bd[4] = dup2_(b1.x); bd[5] = dup2_(b1.y);
            bd[6] = dup2_(b1.z); bd[7] = dup2_(b1.w);
            #pragma unroll
            for (int j = 0; j < 8; j++) {
                acc2[0][j] = fma2_(a01.x, bd[j], acc2[0][j]);
                acc2[1][j] = fma2_(a01.y, bd[j], acc2[1][j]);
                acc2[2][j] = fma2_(a23.x, bd[j], acc2[2][j]);
                acc2[3][j] = fma2_(a23.y, bd[j], acc2[3][j]);
            }
        }
    }

    // Epilogue: write partials, row-pair at a time.
    #pragma unroll
    for (int p = 0; p < 4; p++) {
        float r0[8], r1[8];
        #pragma unroll
        for (int j = 0; j < 8; j++) {
            float2 v = unpack2_(acc2[p][j]);
            r0[j] = v.x; r1[j] = v.y;
        }
        float* o0 = outp + (size_t)(ty * 8 + 2 * p + 0) * outStride + tx * 8;
        float* o1 = outp + (size_t)(ty * 8 + 2 * p + 1) * outStride + tx * 8;
        *(float4*)(o0)     = make_float4(r0[0], r0[1], r0[2], r0[3]);
        *(float4*)(o0 + 4) = make_float4(r0[4], r0[5], r0[6], r0[7]);
        *(float4*)(o1)     = make_float4(r1[0], r1[1], r1[2], r1[3]);
        *(float4*)(o1 + 4) = make_float4(r1[4], r1[5], r1[6], r1[7]);
    }
}

// ---------------------------------------------------------------------------
// Persistent recurrence: 128 CTAs x 256 thr, 4 phases/step with split-K.
//  A-gemm : 2M x 16N x 4K CTAs, 128x128x256 partials -> g_PA
//  A-red  : sum 4 partials + sigmoid -> g_z / g_rh
//  B-gemm : 2M x 8N x 8K CTAs, 128x128x128 partials -> g_PB
//  B-red  : sum 8 partials + tanh + h update -> g_h
// ---------------------------------------------------------------------------
__global__ __launch_bounds__(NTHR) void gru_persistent(
    const float* __restrict__ Uz, const float* __restrict__ Ur,
    const float* __restrict__ U,  float* __restrict__ out)
{
    __shared__ float As[2][16][136];
    __shared__ float Bs[2][16][128];

    const int cta = blockIdx.x;
    const int tid = threadIdx.x;
    unsigned bcount = 0;

    // ---- step 0: h = sigmoid(Gz[0]) * tanh(Gh[0])  (h0 = 0) ----
    {
        size_t base = (size_t)cta * (BH / GRID);
        #pragma unroll
        for (int v = 0; v < 2; v++) {
            size_t idx = base + (size_t)(v * NTHR + tid) * 4;
            float4 gz = *(const float4*)&g_G[idx];
            float4 gh = *(const float4*)&g_G[2 * TBH + idx];
            float4 h;
            h.x = sigmoidf_(gz.x) * tanhf(gh.x);
            h.y = sigmoidf_(gz.y) * tanhf(gh.y);
            h.z = sigmoidf_(gz.z) * tanhf(gh.z);
            h.w = sigmoidf_(gz.w) * tanhf(gh.w);
            *(float4*)&g_h[idx] = h;
        }
    }
    bcount++; grid_barrier(bcount * GRID);

    // A-gemm decomposition
    const int ksA = cta >> 5;              // 0..3
    const int remA = cta & 31;
    const int msA = remA >> 4;             // 0..1
    const int nsA = remA & 15;             // 0..15
    const float* BsrcA = (nsA < 8) ? (Uz + nsA * 128) : (Ur + (nsA - 8) * 128);

    // B-gemm decomposition
    const int ksB = cta >> 4;              // 0..7
    const int remB = cta & 15;
    const int msB = remB >> 3;             // 0..1
    const int nsB = remB & 7;              // 0..7

    for (int t = 1; t < T_; t++) {
        // ===== A-gemm: partial (h @ [Uz|Ur]) ================================
        gemm128_tile(
            g_h + (size_t)msA * 128 * H_ + ksA * 256,
            BsrcA + (size_t)ksA * 256 * H_,
            g_PA + ((size_t)ksA * 256 + msA * 128) * 2048 + nsA * 128,
            2048, 16, As, Bs, tid);
        bcount++; grid_barrier(bcount * GRID);

        // ===== A-red: z = sig(sum+Gz), rh = sig(sum+Gr)*h ===================
        {
            const float4* PA4 = (const float4*)g_PA;
            #pragma unroll
            for (int j = 0; j < 4; j++) {
                int idx4 = cta * 1024 + j * 256 + tid;
                int m  = idx4 >> 9;          // 512 float4 per 2048-row
                int c4 = idx4 & 511;
                float4 s0 = __ldcg(PA4 + idx4);
                float4 s1 = __ldcg(PA4 + idx4 + 131072);
                float4 s2 = __ldcg(PA4 + idx4 + 262144);
                float4 s3 = __ldcg(PA4 + idx4 + 393216);
                float4 s;
                s.x = (s0.x + s1.x) + (s2.x + s3.x);
                s.y = (s0.y + s1.y) + (s2.y + s3.y);
                s.z = (s0.z + s1.z) + (s2.z + s3.z);
                s.w = (s0.w + s1.w) + (s2.w + s3.w);
                if (c4 < 256) {
                    int n = c4 * 4;
                    float4 g = *(const float4*)(g_G + (size_t)t * BH + m * H_ + n);
                    float4 z;
                    z.x = sigmoidf_(s.x + g.x);
                    z.y = sigmoidf_(s.y + g.y);
                    z.z = sigmoidf_(s.z + g.z);
                    z.w = sigmoidf_(s.w + g.w);
                    *(float4*)&g_z[m * H_ + n] = z;
                } else {
                    int n = (c4 - 256) * 4;
                    float4 g = *(const float4*)(g_G + TBH + (size_t)t * BH + m * H_ + n);
                    float4 h = __ldcg((const float4*)&g_h[m * H_ + n]);
                    float4 rh;
                    rh.x = sigmoidf_(s.x + g.x) * h.x;
                    rh.y = sigmoidf_(s.y + g.y) * h.y;
                    rh.z = sigmoidf_(s.z + g.z) * h.z;
                    rh.w = sigmoidf_(s.w + g.w) * h.w;
                    *(float4*)&g_rh[m * H_ + n] = rh;
                }
            }
        }
        bcount++; grid_barrier(bcount * GRID);

        // ===== B-gemm: partial (rh @ U) =====================================
        gemm128_tile(
            g_rh + (size_t)msB * 128 * H_ + ksB * 128,
            U + (size_t)ksB * 128 * H_ + nsB * 128,
            g_PB + ((size_t)ksB * 256 + msB * 128) * 1024 + nsB * 128,
            1024, 8, As, Bs, tid);
        bcount++; grid_barrier(bcount * GRID);

        // ===== B-red: h = (1-z)h + z*tanh(sum+Gh) ===========================
        {
            const float4* PB4 = (const float4*)g_PB;
            #pragma unroll
            for (int j = 0; j < 2; j++) {
                int idx4 = cta * 512 + j * 256 + tid;
                int m  = idx4 >> 8;          // 256 float4 per 1024-row
                int c4 = idx4 & 255;
                int n  = c4 * 4;
                float4 s = __ldcg(PB4 + idx4);
                #pragma unroll
                for (int ks = 1; ks < 8; ks++) {
                    float4 p = __ldcg(PB4 + idx4 + ks * 65536);
                    s.x += p.x; s.y += p.y; s.z += p.z; s.w += p.w;
                }
                float4 g = *(const float4*)(g_G + 2 * TBH + (size_t)t * BH + m * H_ + n);
                float4 z = __ldcg((const float4*)&g_z[m * H_ + n]);
                float4 h = __ldcg((const float4*)&g_h[m * H_ + n]);
                float4 hn;
                hn.x = (1.0f - z.x) * h.x + z.x * tanhf(s.x + g.x);
                hn.y = (1.0f - z.y) * h.y + z.y * tanhf(s.y + g.y);
                hn.z = (1.0f - z.z) * h.z + z.z * tanhf(s.z + g.z);
                hn.w = (1.0f - z.w) * h.w + z.w * tanhf(s.w + g.w);
                *(float4*)&g_h[m * H_ + n] = hn;
            }
        }
        bcount++; grid_barrier(bcount * GRID);
    }

    // ---- copy out ----
    {
        size_t base = (size_t)cta * (BH / GRID);
        #pragma unroll
        for (int v = 0; v < 2; v++) {
            size_t idx = base + (size_t)(v * NTHR + tid) * 4;
            float4 h = __ldcg((const float4*)&g_h[idx]);
            *(float4*)&out[idx] = h;
        }
    }
}

// ---------------------------------------------------------------------------
extern "C" void kernel_launch(void* const* d_in, const int* in_sizes, int n_in,
                              void* d_out, int out_size)
{
    const float* x  = (const float*)d_in[0];  // [B,T,D]
    const float* W  = (const float*)d_in[1];  // [D,H]
    const float* U  = (const float*)d_in[2];  // [H,H]
    const float* Wz = (const float*)d_in[3];
    const float* Uz = (const float*)d_in[4];
    const float* Wr = (const float*)d_in[5];
    const float* Ur = (const float*)d_in[6];
    const float* b  = (const float*)d_in[7];
    const float* bz = (const float*)d_in[8];
    const float* br = (const float*)d_in[9];

    (void)in_sizes; (void)n_in; (void)out_size;

    // Node 1: input projections (biases folded) + barrier-counter reset.
    dim3 g1(H_ / 128, (B_ * T_) / 128, 3);
    xproj_kernel<<<g1, 256>>>(x, Wz, Wr, W, bz, br, b);

    // Node 2: entire recurrence, one persistent kernel.
    gru_persistent<<<GRID, NTHR>>>(Uz, Ur, U, (float*)d_out);
}